// round 4
// baseline (speedup 1.0000x reference)
#include <cuda_runtime.h>
#include <cstdint>

// Fixed problem shapes
#define NST  32      // categorical variables
#define SS   32      // classes per categorical
#define EE   128     // embedding size

// libdevice accurate logf — the exact function XLA GPU lowers log.f32 to.
extern "C" __device__ float __nv_logf(float);

// rotate-left via one IMAD.WIDE.U32 on the FMA pipe:
// 64-bit product x * 2^r  ->  lo = x<<r, hi = x>>(32-r); rot = hi | lo.
// inline asm prevents ptxas from strength-reducing the multiply to shifts.
__device__ __forceinline__ uint32_t rotl_wide(uint32_t x, uint32_t pow2r) {
    uint64_t p;
    asm("mul.wide.u32 %0, %1, %2;" : "=l"(p) : "r"(x), "r"(pow2r));
    return (uint32_t)(p >> 32) | (uint32_t)p;   // (hi|lo)^next -> fuses to LOP3
}

// Threefry-2x32, 20 rounds, key=(0,42), partitionable layout:
// counter=(hi=0, lo=i); bits = o0^o1.  (Confirmed bit-exact R2/R3.)
// Half the rounds rotate via the alu-pipe funnel shift, half via the
// fma-pipe IMAD.WIDE trick — balances the two issue pipes.
__device__ __forceinline__ uint32_t threefry_bits(uint32_t i) {
    const uint32_t k0 = 0u;
    const uint32_t k1 = 42u;
    const uint32_t k2 = 0u ^ 42u ^ 0x1BD11BDAu;
    uint32_t x0 = 0u + k0;
    uint32_t x1 = i + k1;
#define TF_S(r) { x0 += x1; x1 = __funnelshift_l(x1, x1, (r)) ^ x0; }
#define TF_W(r) { x0 += x1; x1 = rotl_wide(x1, 1u << (r)) ^ x0; }
    TF_S(13) TF_W(15) TF_S(26) TF_W(6)   x0 += k1; x1 += k2 + 1u;
    TF_S(17) TF_W(29) TF_S(16) TF_W(24)  x0 += k2; x1 += k0 + 2u;
    TF_S(13) TF_W(15) TF_S(26) TF_W(6)   x0 += k0; x1 += k1 + 3u;
    TF_S(17) TF_W(29) TF_S(16) TF_W(24)  x0 += k1; x1 += k2 + 4u;
    TF_S(13) TF_W(15) TF_S(26) TF_W(6)   x0 += k2; x1 += k0 + 5u;
#undef TF_S
#undef TF_W
    return x0 ^ x1;
}

// bits -> jax uniform(FLT_MIN, 1) -> gumbel, bit-exact vs XLA GPU.
// (float)(bits>>9) is exact (< 2^23); * 2^-23 is exact; equals
// uint_as_float((bits>>9)|0x3F800000) - 1.0f by Sterbenz.
__device__ __forceinline__ float gumbel_from_bits(uint32_t bits) {
    float f = (float)(bits >> 9) * 1.1920928955078125e-7f;  // 2^-23
    float u = fmaxf(f, 1.17549435082228750797e-38f);        // FLT_MIN clamp
    return -__nv_logf(-__nv_logf(u));
}

// order-preserving float -> uint (monotone; equal floats -> equal keys)
__device__ __forceinline__ uint32_t float_ordered(float v) {
    uint32_t b = __float_as_uint(v);
    return b ^ (uint32_t)(((int32_t)b >> 31) | (int32_t)0x80000000);
}

__global__ void __launch_bounds__(256)
categorical_encoder_kernel(const float* __restrict__ x,
                           const float* __restrict__ codebook,
                           float* __restrict__ out) {
    const int gwarp = (blockIdx.x * blockDim.x + threadIdx.x) >> 5;  // 0..65535
    const int lane  = threadIdx.x & 31;

    // 4 rows per warp
    const int rbase = gwarp << 2;
    const uint32_t ebase = ((uint32_t)rbase << 5) + (uint32_t)lane;

    uint32_t bits[4];
#pragma unroll
    for (int j = 0; j < 4; j++) bits[j] = threefry_bits(ebase + (uint32_t)j * SS);

    float v[4];
#pragma unroll
    for (int j = 0; j < 4; j++)
        v[j] = gumbel_from_bits(bits[j]) + __ldg(&x[ebase + (uint32_t)j * SS]);

#pragma unroll
    for (int j = 0; j < 4; j++) {
        const uint32_t u    = float_ordered(v[j]);
        const uint32_t umax = __reduce_max_sync(0xFFFFFFFFu, u);
        const uint32_t bal  = __ballot_sync(0xFFFFFFFFu, u == umax);
        const int idx = __ffs(bal) - 1;   // first-index tiebreak (jnp.argmax)

        const int r = rbase + j;
        const int n = r & (NST - 1);
        const float4* src = reinterpret_cast<const float4*>(
            codebook + ((size_t)n * SS + idx) * EE);
        float4* dst = reinterpret_cast<float4*>(out + (size_t)r * EE);
        dst[lane] = src[lane];
    }
}

extern "C" void kernel_launch(void* const* d_in, const int* in_sizes, int n_in,
                              void* d_out, int out_size) {
    const float* x        = (const float*)d_in[0];
    const float* codebook = (const float*)d_in[1];
    if (n_in >= 2 && in_sizes[0] < in_sizes[1]) {
        x        = (const float*)d_in[1];
        codebook = (const float*)d_in[0];
    }
    float* out = (float*)d_out;

    // 262144 rows, 4 rows/warp, 8 warps/block -> 8192 blocks
    categorical_encoder_kernel<<<8192, 256>>>(x, codebook, out);
}

// round 5
// speedup vs baseline: 1.0596x; 1.0596x over previous
#include <cuda_runtime.h>
#include <cstdint>

// Fixed problem shapes
#define NST  32      // categorical variables
#define SS   32      // classes per categorical
#define EE   128     // embedding size

// libdevice accurate logf — the exact function XLA GPU lowers log.f32 to.
extern "C" __device__ float __nv_logf(float);

// Threefry-2x32, 20 rounds, key=(0,42), partitionable layout:
// counter=(hi=0, lo=i); bits = o0^o1.  (Confirmed bit-exact R2/R3.)
__device__ __forceinline__ uint32_t threefry_bits(uint32_t i) {
    const uint32_t k0 = 0u;
    const uint32_t k1 = 42u;
    const uint32_t k2 = 0u ^ 42u ^ 0x1BD11BDAu;
    uint32_t x0 = 0u + k0;
    uint32_t x1 = i + k1;
#define TF_RND(r) { x0 += x1; x1 = __funnelshift_l(x1, x1, (r)) ^ x0; }
    TF_RND(13) TF_RND(15) TF_RND(26) TF_RND(6)   x0 += k1; x1 += k2 + 1u;
    TF_RND(17) TF_RND(29) TF_RND(16) TF_RND(24)  x0 += k2; x1 += k0 + 2u;
    TF_RND(13) TF_RND(15) TF_RND(26) TF_RND(6)   x0 += k0; x1 += k1 + 3u;
    TF_RND(17) TF_RND(29) TF_RND(16) TF_RND(24)  x0 += k1; x1 += k2 + 4u;
    TF_RND(13) TF_RND(15) TF_RND(26) TF_RND(6)   x0 += k2; x1 += k0 + 5u;
#undef TF_RND
    return x0 ^ x1;
}

// bits -> jax uniform(FLT_MIN,1) -> gumbel, bit-exact vs XLA GPU.
// (float)(bits>>9) exact (< 2^23); *2^-23 exact; equals
// uint_as_float((bits>>9)|0x3F800000) - 1.0f by Sterbenz.
// I2F issues on the conversion pipe — relieves alu vs the LOP3 form.
__device__ __forceinline__ float gumbel_from_bits(uint32_t bits) {
    float f = (float)(bits >> 9) * 1.1920928955078125e-7f;  // 2^-23
    float u = fmaxf(f, 1.17549435082228750797e-38f);        // FLT_MIN clamp
    return -__nv_logf(-__nv_logf(u));
}

// order-preserving float -> uint (monotone; equal floats -> equal keys)
__device__ __forceinline__ uint32_t float_ordered(float v) {
    uint32_t b = __float_as_uint(v);
    return b ^ (uint32_t)(((int32_t)b >> 31) | (int32_t)0x80000000);
}

#define RPW 8   // rows per warp

__global__ void __launch_bounds__(256)
categorical_encoder_kernel(const float* __restrict__ x,
                           const float* __restrict__ codebook,
                           float* __restrict__ out) {
    const int gwarp = (blockIdx.x * blockDim.x + threadIdx.x) >> 5;  // 0..32767
    const int lane  = threadIdx.x & 31;

    const int rbase = gwarp * RPW;
    const uint32_t ebase = ((uint32_t)rbase << 5) + (uint32_t)lane;

    // prefetch logits (8 independent LDGs, batched for MLP)
    float lgt[RPW];
#pragma unroll
    for (int j = 0; j < RPW; j++)
        lgt[j] = __ldg(&x[ebase + (uint32_t)j * SS]);

    // 8 independent threefry chains (ILP covers the 4-cyc alu latency)
    uint32_t bits[RPW];
#pragma unroll
    for (int j = 0; j < RPW; j++)
        bits[j] = threefry_bits(ebase + (uint32_t)j * SS);

    float v[RPW];
#pragma unroll
    for (int j = 0; j < RPW; j++)
        v[j] = gumbel_from_bits(bits[j]) + lgt[j];

#pragma unroll
    for (int j = 0; j < RPW; j++) {
        const uint32_t u    = float_ordered(v[j]);
        const uint32_t umax = __reduce_max_sync(0xFFFFFFFFu, u);
        const uint32_t bal  = __ballot_sync(0xFFFFFFFFu, u == umax);
        const int idx = __ffs(bal) - 1;   // first-index tiebreak (jnp.argmax)

        const int r = rbase + j;
        const int n = r & (NST - 1);
        const float4* src = reinterpret_cast<const float4*>(
            codebook + ((size_t)n * SS + idx) * EE);
        float4* dst = reinterpret_cast<float4*>(out + (size_t)r * EE);
        dst[lane] = src[lane];
    }
}

extern "C" void kernel_launch(void* const* d_in, const int* in_sizes, int n_in,
                              void* d_out, int out_size) {
    const float* x        = (const float*)d_in[0];
    const float* codebook = (const float*)d_in[1];
    if (n_in >= 2 && in_sizes[0] < in_sizes[1]) {
        x        = (const float*)d_in[1];
        codebook = (const float*)d_in[0];
    }
    float* out = (float*)d_out;

    // 262144 rows, 8 rows/warp, 8 warps/block -> 4096 blocks
    categorical_encoder_kernel<<<4096, 256>>>(x, codebook, out);
}

// round 6
// speedup vs baseline: 1.1510x; 1.0863x over previous
#include <cuda_runtime.h>
#include <cstdint>

// Fixed problem shapes
#define NST  32      // categorical variables
#define SS   32      // classes per categorical
#define EE   128     // embedding size

// libdevice accurate logf — the exact function XLA GPU lowers log.f32 to.
extern "C" __device__ float __nv_logf(float);

// Threefry-2x32, 20 rounds, key=(0,42), partitionable layout:
// counter=(hi=0, lo=i); bits = o0^o1.  (Confirmed bit-exact R2..R5.)
__device__ __forceinline__ uint32_t threefry_bits(uint32_t i) {
    const uint32_t k0 = 0u;
    const uint32_t k1 = 42u;
    const uint32_t k2 = 0u ^ 42u ^ 0x1BD11BDAu;
    uint32_t x0 = 0u + k0;
    uint32_t x1 = i + k1;
#define TF_RND(r) { x0 += x1; x1 = __funnelshift_l(x1, x1, (r)) ^ x0; }
    TF_RND(13) TF_RND(15) TF_RND(26) TF_RND(6)   x0 += k1; x1 += k2 + 1u;
    TF_RND(17) TF_RND(29) TF_RND(16) TF_RND(24)  x0 += k2; x1 += k0 + 2u;
    TF_RND(13) TF_RND(15) TF_RND(26) TF_RND(6)   x0 += k0; x1 += k1 + 3u;
    TF_RND(17) TF_RND(29) TF_RND(16) TF_RND(24)  x0 += k1; x1 += k2 + 4u;
    TF_RND(13) TF_RND(15) TF_RND(26) TF_RND(6)   x0 += k2; x1 += k0 + 5u;
#undef TF_RND
    return x0 ^ x1;
}

// bits -> jax uniform(FLT_MIN,1) -> gumbel, bit-exact vs XLA GPU.
// (float)(bits>>9) exact (<2^23); *2^-23 exact; equals the |0x3F800000 - 1.0f
// form by Sterbenz. I2F issues off the alu/fma pipes.
__device__ __forceinline__ float gumbel_from_bits(uint32_t bits) {
    float f = (float)(bits >> 9) * 1.1920928955078125e-7f;  // 2^-23
    float u = fmaxf(f, 1.17549435082228750797e-38f);        // FLT_MIN clamp
    return -__nv_logf(-__nv_logf(u));
}

// order-preserving float -> uint (monotone; equal floats -> equal keys)
__device__ __forceinline__ uint32_t float_ordered(float v) {
    uint32_t b = __float_as_uint(v);
    return b ^ (uint32_t)(((int32_t)b >> 31) | (int32_t)0x80000000);
}

#define RPW 8   // rows per warp

__global__ void __launch_bounds__(256)
categorical_encoder_kernel(const float* __restrict__ x,
                           const float* __restrict__ codebook,
                           float* __restrict__ out) {
    const int gwarp = (blockIdx.x * blockDim.x + threadIdx.x) >> 5;  // 0..32767
    const int lane  = threadIdx.x & 31;

    const int rbase = gwarp * RPW;
    const uint32_t ebase = ((uint32_t)rbase << 5) + (uint32_t)lane;

    // prefetch logits (8 independent LDGs)
    float lgt[RPW];
#pragma unroll
    for (int j = 0; j < RPW; j++)
        lgt[j] = __ldg(&x[ebase + (uint32_t)j * SS]);

    // 8 independent threefry chains
    uint32_t bits[RPW];
#pragma unroll
    for (int j = 0; j < RPW; j++)
        bits[j] = threefry_bits(ebase + (uint32_t)j * SS);

    float v[RPW];
#pragma unroll
    for (int j = 0; j < RPW; j++)
        v[j] = gumbel_from_bits(bits[j]) + lgt[j];

    // ---- phase 1: all argmax indices (batched REDUX/ballot) ----
    int idx[RPW];
#pragma unroll
    for (int j = 0; j < RPW; j++) {
        const uint32_t u    = float_ordered(v[j]);
        const uint32_t umax = __reduce_max_sync(0xFFFFFFFFu, u);
        const uint32_t bal  = __ballot_sync(0xFFFFFFFFu, u == umax);
        idx[j] = __ffs(bal) - 1;   // first-index tiebreak (jnp.argmax)
    }

    // ---- phase 2: all 8 codebook gathers in flight (MLP=8) ----
    // rbase % 8 == 0 and NST == 32 -> n = n0 + j with no wrap for j < 8
    const int n0 = rbase & (NST - 1);
    const float4* cb = reinterpret_cast<const float4*>(codebook)
                       + ((size_t)n0 * SS) * (EE / 4) + lane;
    float4 tmp[RPW];
#pragma unroll
    for (int j = 0; j < RPW; j++)
        tmp[j] = cb[(size_t)(j * SS + idx[j]) * (EE / 4)];

    // ---- phase 3: all 8 stores ----
    float4* dst = reinterpret_cast<float4*>(out) + (size_t)rbase * (EE / 4) + lane;
#pragma unroll
    for (int j = 0; j < RPW; j++)
        dst[(size_t)j * (EE / 4)] = tmp[j];
}

extern "C" void kernel_launch(void* const* d_in, const int* in_sizes, int n_in,
                              void* d_out, int out_size) {
    const float* x        = (const float*)d_in[0];
    const float* codebook = (const float*)d_in[1];
    if (n_in >= 2 && in_sizes[0] < in_sizes[1]) {
        x        = (const float*)d_in[1];
        codebook = (const float*)d_in[0];
    }
    float* out = (float*)d_out;

    // 262144 rows, 8 rows/warp, 8 warps/block -> 4096 blocks
    categorical_encoder_kernel<<<4096, 256>>>(x, codebook, out);
}

// round 7
// speedup vs baseline: 1.1537x; 1.0023x over previous
#include <cuda_runtime.h>
#include <cstdint>

// Fixed problem shapes
#define NST  32      // categorical variables
#define SS   32      // classes per categorical
#define EE   128     // embedding size

// libdevice accurate logf — the exact function XLA GPU lowers log.f32 to.
extern "C" __device__ float __nv_logf(float);

// Opaque 1 — ptxas cannot const-fold, forcing mad.lo below to stay IMAD
// (fma pipe) instead of being canonicalized to IADD3 (alu pipe).
__device__ __forceinline__ uint32_t opaque_one() {
    uint32_t v;
    asm("mov.b32 %0, 1;" : "=r"(v));
    return v;
}

// a + b issued as IMAD on the fma pipe: a*one + b, one opaque.
__device__ __forceinline__ uint32_t add_fma(uint32_t a, uint32_t one, uint32_t b) {
    uint32_t r;
    asm("mad.lo.u32 %0, %1, %2, %3;" : "=r"(r) : "r"(a), "r"(one), "r"(b));
    return r;
}

// Threefry-2x32, 20 rounds, key=(0,42), partitionable layout:
// counter=(hi=0, lo=i); bits = o0^o1.  (Confirmed bit-exact R2..R6.)
// Round adds go to the fma pipe (IMAD) — SHF/LOP3 are alu-only, so the
// default IADD3/IMAD alternation leaves alu 2x oversubscribed.
__device__ __forceinline__ uint32_t threefry_bits(uint32_t i, uint32_t one) {
    const uint32_t k0 = 0u;
    const uint32_t k1 = 42u;
    const uint32_t k2 = 0u ^ 42u ^ 0x1BD11BDAu;
    uint32_t x0 = 0u + k0;
    uint32_t x1 = i + k1;
#define TF_RND(r) { x0 = add_fma(x0, one, x1); \
                    x1 = __funnelshift_l(x1, x1, (r)) ^ x0; }
    TF_RND(13) TF_RND(15) TF_RND(26) TF_RND(6)   x0 += k1; x1 += k2 + 1u;
    TF_RND(17) TF_RND(29) TF_RND(16) TF_RND(24)  x0 += k2; x1 += k0 + 2u;
    TF_RND(13) TF_RND(15) TF_RND(26) TF_RND(6)   x0 += k0; x1 += k1 + 3u;
    TF_RND(17) TF_RND(29) TF_RND(16) TF_RND(24)  x0 += k1; x1 += k2 + 4u;
    TF_RND(13) TF_RND(15) TF_RND(26) TF_RND(6)   x0 += k2; x1 += k0 + 5u;
#undef TF_RND
    return x0 ^ x1;
}

// bits -> jax uniform(FLT_MIN,1) -> gumbel, bit-exact vs XLA GPU.
// (float)(bits>>9) exact (<2^23); *2^-23 exact; equals |0x3F800000 - 1.0f
// by Sterbenz. I2F issues off the alu/fma pipes.
__device__ __forceinline__ float gumbel_from_bits(uint32_t bits) {
    float f = (float)(bits >> 9) * 1.1920928955078125e-7f;  // 2^-23
    float u = fmaxf(f, 1.17549435082228750797e-38f);        // FLT_MIN clamp
    return -__nv_logf(-__nv_logf(u));
}

// order-preserving float -> uint (monotone; equal floats -> equal keys)
__device__ __forceinline__ uint32_t float_ordered(float v) {
    uint32_t b = __float_as_uint(v);
    return b ^ (uint32_t)(((int32_t)b >> 31) | (int32_t)0x80000000);
}

#define RPW 8   // rows per warp

__global__ void __launch_bounds__(256)
categorical_encoder_kernel(const float* __restrict__ x,
                           const float* __restrict__ codebook,
                           float* __restrict__ out) {
    const int gwarp = (blockIdx.x * blockDim.x + threadIdx.x) >> 5;  // 0..32767
    const int lane  = threadIdx.x & 31;
    const uint32_t one = opaque_one();

    const int rbase = gwarp * RPW;
    const uint32_t ebase = ((uint32_t)rbase << 5) + (uint32_t)lane;

    // prefetch logits (8 independent LDGs)
    float lgt[RPW];
#pragma unroll
    for (int j = 0; j < RPW; j++)
        lgt[j] = __ldg(&x[ebase + (uint32_t)j * SS]);

    // 8 independent threefry chains
    uint32_t bits[RPW];
#pragma unroll
    for (int j = 0; j < RPW; j++)
        bits[j] = threefry_bits(ebase + (uint32_t)j * SS, one);

    float v[RPW];
#pragma unroll
    for (int j = 0; j < RPW; j++)
        v[j] = gumbel_from_bits(bits[j]) + lgt[j];

    // ---- phase 1: all argmax indices (batched REDUX/ballot) ----
    int idx[RPW];
#pragma unroll
    for (int j = 0; j < RPW; j++) {
        const uint32_t u    = float_ordered(v[j]);
        const uint32_t umax = __reduce_max_sync(0xFFFFFFFFu, u);
        const uint32_t bal  = __ballot_sync(0xFFFFFFFFu, u == umax);
        idx[j] = __ffs(bal) - 1;   // first-index tiebreak (jnp.argmax)
    }

    // ---- phase 2: all 8 codebook gathers in flight (MLP) ----
    // rbase % 8 == 0 and NST == 32 -> n = n0 + j with no wrap for j < 8
    const int n0 = rbase & (NST - 1);
    const float4* cb = reinterpret_cast<const float4*>(codebook)
                       + ((size_t)n0 * SS) * (EE / 4) + lane;
    float4 tmp[RPW];
#pragma unroll
    for (int j = 0; j < RPW; j++)
        tmp[j] = cb[(size_t)(j * SS + idx[j]) * (EE / 4)];

    // ---- phase 3: all 8 stores ----
    float4* dst = reinterpret_cast<float4*>(out) + (size_t)rbase * (EE / 4) + lane;
#pragma unroll
    for (int j = 0; j < RPW; j++)
        dst[(size_t)j * (EE / 4)] = tmp[j];
}

extern "C" void kernel_launch(void* const* d_in, const int* in_sizes, int n_in,
                              void* d_out, int out_size) {
    const float* x        = (const float*)d_in[0];
    const float* codebook = (const float*)d_in[1];
    if (n_in >= 2 && in_sizes[0] < in_sizes[1]) {
        x        = (const float*)d_in[1];
        codebook = (const float*)d_in[0];
    }
    float* out = (float*)d_out;

    // 262144 rows, 8 rows/warp, 8 warps/block -> 4096 blocks
    categorical_encoder_kernel<<<4096, 256>>>(x, codebook, out);
}